// round 2
// baseline (speedup 1.0000x reference)
#include <cuda_runtime.h>
#include <math.h>

constexpr int kD = 2048;   // hidden
constexpr int kE = 32;     // experts
constexpr int kK = 8;      // top-k
constexpr int kI = 1024;   // intermediate
constexpr int kMaxT = 8192;
constexpr int kMaxRows = kMaxT * kK;   // 65536

// ---------------- scratch (no dynamic allocation allowed) ----------------
__device__ float g_H[(size_t)kMaxRows * kI];   // 256 MB: scaled SwiGLU activations per routed row
__device__ int   g_topi[kMaxRows];
__device__ float g_topw[kMaxRows];
__device__ int   g_rowtok[kMaxRows];
__device__ float g_rowscale[kMaxRows];
__device__ int   g_counts[kE];
__device__ int   g_offsets[kE + 1];
__device__ int   g_cursor[kE];
__device__ float g_sumprob[kE];

// ---------------- reset ----------------
__global__ void zero_kernel(float* __restrict__ out, size_t n) {
    size_t i = (size_t)blockIdx.x * blockDim.x + threadIdx.x;
    size_t stride = (size_t)gridDim.x * blockDim.x;
    for (; i < n; i += stride) out[i] = 0.f;
    if (blockIdx.x == 0 && threadIdx.x < kE) {
        g_counts[threadIdx.x] = 0;
        g_cursor[threadIdx.x] = 0;
        g_sumprob[threadIdx.x] = 0.f;
    }
}

// ---------------- router: logits, full softmax (aux), top-8 + softmax weights ----------------
__global__ void router_kernel(const float* __restrict__ x,
                              const float* __restrict__ Wgate, int T) {
    int warp = (blockIdx.x * blockDim.x + threadIdx.x) >> 5;
    int lane = threadIdx.x & 31;
    if (warp >= T) return;
    const float* xt = x + (size_t)warp * kD;

    float acc = 0.f;
#pragma unroll 4
    for (int d = 0; d < kD; ++d) acc += xt[d] * Wgate[d * kE + lane];

    // full softmax over 32 experts -> aux-loss accumulation
    float m = acc;
#pragma unroll
    for (int o = 16; o; o >>= 1) m = fmaxf(m, __shfl_xor_sync(0xffffffffu, m, o));
    float p = __expf(acc - m);
    float s = p;
#pragma unroll
    for (int o = 16; o; o >>= 1) s += __shfl_xor_sync(0xffffffffu, s, o);
    atomicAdd(&g_sumprob[lane], p / s);

    // top-8 (ties -> lowest index, matching lax.top_k)
    float v = acc;
    float topv[kK]; int topi[kK];
#pragma unroll
    for (int k = 0; k < kK; ++k) {
        float bv = v; int bi = lane;
#pragma unroll
        for (int o = 16; o; o >>= 1) {
            float ov = __shfl_xor_sync(0xffffffffu, bv, o);
            int   oi = __shfl_xor_sync(0xffffffffu, bi, o);
            if (ov > bv || (ov == bv && oi < bi)) { bv = ov; bi = oi; }
        }
        topv[k] = bv; topi[k] = bi;
        if (lane == bi) v = -INFINITY;
    }

    // softmax over the 8 selected logits (all lanes compute identical values)
    float mx = topv[0];
    float w[kK]; float se = 0.f;
#pragma unroll
    for (int k = 0; k < kK; ++k) { w[k] = __expf(topv[k] - mx); se += w[k]; }
#pragma unroll
    for (int k = 0; k < kK; ++k) {
        if (lane == k) {
            g_topi[warp * kK + k] = topi[k];
            g_topw[warp * kK + k] = w[k] / se;
            atomicAdd(&g_counts[topi[k]], 1);
        }
    }
}

__global__ void offsets_kernel() {
    if (threadIdx.x == 0) {
        int s = 0;
        for (int e = 0; e < kE; ++e) { g_offsets[e] = s; s += g_counts[e]; }
        g_offsets[kE] = s;
    }
}

__global__ void scatter_kernel(int T) {
    int idx = blockIdx.x * blockDim.x + threadIdx.x;
    if (idx >= T * kK) return;
    int e = g_topi[idx];
    int pos = g_offsets[e] + atomicAdd(&g_cursor[e], 1);
    g_rowtok[pos]   = idx / kK;
    g_rowscale[pos] = g_topw[idx];
}

__global__ void aux_kernel(float* __restrict__ out, int T, int out_size) {
    if (threadIdx.x == 0 && (size_t)out_size > (size_t)T * kD) {
        float a = 0.f;
        for (int e = 0; e < kE; ++e) a += g_sumprob[e] * (float)g_counts[e];
        out[(size_t)T * kD] = a / ((float)T * (float)T);
    }
}

__device__ __forceinline__ float silu_f(float v) { return v / (1.f + __expf(-v)); }

// ---------------- GEMM1: H[r, :] = w_r * silu(x@Wg) * (x@Wu), grouped by expert ----------------
// tile 128(M) x 64(N), BK=16, 256 threads, each 8x4 per GEMM (gate+up share A)
__global__ __launch_bounds__(256) void gemm1_kernel(const float* __restrict__ x,
                                                    const float* __restrict__ Wg,
                                                    const float* __restrict__ Wu) {
    const int e = blockIdx.z;
    const int base = g_offsets[e];
    const int count = g_offsets[e + 1] - base;
    const int m0 = blockIdx.y * 128;
    if (m0 >= count) return;
    const int n0 = blockIdx.x * 64;

    __shared__ float As[16][132];
    __shared__ float Bg[16][64];
    __shared__ float Bu[16][64];
    __shared__ int   toks[128];
    __shared__ float scl[128];

    const int tid = threadIdx.x;
    if (tid < 128) {
        int r = m0 + tid;
        if (r < count) { toks[tid] = g_rowtok[base + r]; scl[tid] = g_rowscale[base + r]; }
        else           { toks[tid] = -1;                 scl[tid] = 0.f; }
    }
    __syncthreads();

    const int lar = tid >> 1;          // row 0..127
    const int lak = (tid & 1) * 8;     // k offset 0 or 8
    const int atok = toks[lar];
    const float* aptr = (atok >= 0) ? (x + (size_t)atok * kD + lak) : nullptr;

    const int lbk = tid >> 4;          // k row 0..15
    const int lbn = (tid & 15) * 4;    // n 0..60
    const float* bgp = Wg + ((size_t)e * kD + lbk) * kI + n0 + lbn;
    const float* bup = Wu + ((size_t)e * kD + lbk) * kI + n0 + lbn;

    const int tx = tid & 15;           // n quad
    const int ty = tid >> 4;           // m octet

    float cg[8][4] = {};
    float cu[8][4] = {};

    for (int k0 = 0; k0 < kD; k0 += 16) {
        float4 a0 = make_float4(0.f, 0.f, 0.f, 0.f), a1 = a0;
        if (aptr) {
            a0 = *(const float4*)(aptr + k0);
            a1 = *(const float4*)(aptr + k0 + 4);
        }
        float4 bg0 = *(const float4*)(bgp + (size_t)k0 * kI);
        float4 bu0 = *(const float4*)(bup + (size_t)k0 * kI);
        __syncthreads();
        As[lak + 0][lar] = a0.x; As[lak + 1][lar] = a0.y;
        As[lak + 2][lar] = a0.z; As[lak + 3][lar] = a0.w;
        As[lak + 4][lar] = a1.x; As[lak + 5][lar] = a1.y;
        As[lak + 6][lar] = a1.z; As[lak + 7][lar] = a1.w;
        *(float4*)&Bg[lbk][lbn] = bg0;
        *(float4*)&Bu[lbk][lbn] = bu0;
        __syncthreads();
#pragma unroll
        for (int k = 0; k < 16; ++k) {
            const float4 a0v = *(const float4*)&As[k][ty * 8];
            const float4 a1v = *(const float4*)&As[k][ty * 8 + 4];
            const float4 bgv = *(const float4*)&Bg[k][tx * 4];
            const float4 buv = *(const float4*)&Bu[k][tx * 4];
            float am[8] = {a0v.x, a0v.y, a0v.z, a0v.w, a1v.x, a1v.y, a1v.z, a1v.w};
            float bgm[4] = {bgv.x, bgv.y, bgv.z, bgv.w};
            float bum[4] = {buv.x, buv.y, buv.z, buv.w};
#pragma unroll
            for (int i = 0; i < 8; ++i)
#pragma unroll
                for (int j = 0; j < 4; ++j) {
                    cg[i][j] = fmaf(am[i], bgm[j], cg[i][j]);
                    cu[i][j] = fmaf(am[i], bum[j], cu[i][j]);
                }
        }
    }

#pragma unroll
    for (int i = 0; i < 8; ++i) {
        int r = m0 + ty * 8 + i;
        if (r < count) {
            float s = scl[ty * 8 + i];
            float4 hv;
            hv.x = silu_f(cg[i][0]) * cu[i][0] * s;
            hv.y = silu_f(cg[i][1]) * cu[i][1] * s;
            hv.z = silu_f(cg[i][2]) * cu[i][2] * s;
            hv.w = silu_f(cg[i][3]) * cu[i][3] * s;
            *(float4*)(g_H + (size_t)(base + r) * kI + n0 + tx * 4) = hv;
        }
    }
}

// ---------------- GEMM2: out[tok, :] += H[r, :] @ Wd[e], grouped ----------------
// tile 128(M) x 128(N), BK=16, 256 threads, 8x8 per thread, atomicAdd epilogue
__global__ __launch_bounds__(256) void gemm2_kernel(float* __restrict__ out,
                                                    const float* __restrict__ Wd) {
    const int e = blockIdx.z;
    const int base = g_offsets[e];
    const int count = g_offsets[e + 1] - base;
    const int m0 = blockIdx.y * 128;
    if (m0 >= count) return;
    const int n0 = blockIdx.x * 128;

    __shared__ float As[16][132];
    __shared__ float Bs[16][128];
    __shared__ int   toks[128];

    const int tid = threadIdx.x;
    if (tid < 128) {
        int r = m0 + tid;
        toks[tid] = (r < count) ? g_rowtok[base + r] : -1;
    }
    __syncthreads();

    const int lar = tid >> 1;
    const int lak = (tid & 1) * 8;
    const bool avalid = (m0 + lar) < count;
    const float* aptr = g_H + (size_t)(base + m0 + lar) * kI + lak;

    const int lbk = tid >> 4;
    const int lbn = (tid & 15) * 8;
    const float* bp = Wd + ((size_t)e * kI + lbk) * kD + n0 + lbn;

    const int tx = tid & 15;   // n octet
    const int ty = tid >> 4;   // m octet

    float c[8][8] = {};

    for (int k0 = 0; k0 < kI; k0 += 16) {
        float4 a0 = make_float4(0.f, 0.f, 0.f, 0.f), a1 = a0;
        if (avalid) {
            a0 = *(const float4*)(aptr + k0);
            a1 = *(const float4*)(aptr + k0 + 4);
        }
        float4 b0 = *(const float4*)(bp + (size_t)k0 * kD);
        float4 b1 = *(const float4*)(bp + (size_t)k0 * kD + 4);
        __syncthreads();
        As[lak + 0][lar] = a0.x; As[lak + 1][lar] = a0.y;
        As[lak + 2][lar] = a0.z; As[lak + 3][lar] = a0.w;
        As[lak + 4][lar] = a1.x; As[lak + 5][lar] = a1.y;
        As[lak + 6][lar] = a1.z; As[lak + 7][lar] = a1.w;
        *(float4*)&Bs[lbk][lbn]     = b0;
        *(float4*)&Bs[lbk][lbn + 4] = b1;
        __syncthreads();
#pragma unroll
        for (int k = 0; k < 16; ++k) {
            const float4 a0v = *(const float4*)&As[k][ty * 8];
            const float4 a1v = *(const float4*)&As[k][ty * 8 + 4];
            const float4 b0v = *(const float4*)&Bs[k][tx * 8];
            const float4 b1v = *(const float4*)&Bs[k][tx * 8 + 4];
            float am[8] = {a0v.x, a0v.y, a0v.z, a0v.w, a1v.x, a1v.y, a1v.z, a1v.w};
            float bm[8] = {b0v.x, b0v.y, b0v.z, b0v.w, b1v.x, b1v.y, b1v.z, b1v.w};
#pragma unroll
            for (int i = 0; i < 8; ++i)
#pragma unroll
                for (int j = 0; j < 8; ++j)
                    c[i][j] = fmaf(am[i], bm[j], c[i][j]);
        }
    }

#pragma unroll
    for (int i = 0; i < 8; ++i) {
        int r = m0 + ty * 8 + i;
        if (r < count) {
            int tok = toks[ty * 8 + i];
            float* op = out + (size_t)tok * kD + n0 + tx * 8;
#pragma unroll
            for (int j = 0; j < 8; ++j) atomicAdd(&op[j], c[i][j]);
        }
    }
}

// ---------------- launch ----------------
extern "C" void kernel_launch(void* const* d_in, const int* in_sizes, int n_in,
                              void* d_out, int out_size) {
    const float* x     = (const float*)d_in[0];
    const float* Wgate = (const float*)d_in[1];
    const float* Wg    = (const float*)d_in[2];
    const float* Wu    = (const float*)d_in[3];
    const float* Wd    = (const float*)d_in[4];
    float* out = (float*)d_out;

    const int T = in_sizes[0] / kD;   // 8192 tokens

    zero_kernel<<<2048, 256>>>(out, (size_t)out_size);
    router_kernel<<<(T + 7) / 8, 256>>>(x, Wgate, T);
    offsets_kernel<<<1, 32>>>();
    scatter_kernel<<<(T * kK + 255) / 256, 256>>>(T);
    aux_kernel<<<1, 32>>>(out, T, out_size);

    dim3 g1(kI / 64, kMaxT / 128, kE);    // (16, 64, 32)
    gemm1_kernel<<<g1, 256>>>(x, Wg, Wu);

    dim3 g2(kD / 128, kMaxT / 128, kE);   // (16, 64, 32)
    gemm2_kernel<<<g2, 256>>>(out, Wd);
}

// round 7
// speedup vs baseline: 2.0095x; 2.0095x over previous
#include <cuda_runtime.h>
#include <cuda_bf16.h>
#include <math.h>
#include <stdint.h>

constexpr int kD = 2048, kE = 32, kK = 8, kI = 1024, kMaxT = 8192;
constexpr int kMaxRows = kMaxT * kK;   // 65536

// ---------------- scratch: EXACTLY the R2 set (proven) ----------------
__device__ int   g_topi[kMaxRows];
__device__ float g_topw[kMaxRows];
__device__ int   g_rowtok[kMaxRows];
__device__ float g_rowscale[kMaxRows];
__device__ int   g_counts[kE];
__device__ int   g_offsets[kE + 1];
__device__ int   g_cursor[kE];
__device__ float g_sumprob[kE];
__device__ __align__(16) float g_H[(size_t)kMaxRows * kI];   // 256 MB scratch

// ---------------- helpers ----------------
__device__ __forceinline__ void mma_bf16(float* c, const uint32_t* a, const uint32_t* b) {
    asm volatile(
        "mma.sync.aligned.m16n8k16.row.col.f32.bf16.bf16.f32 "
        "{%0,%1,%2,%3}, {%4,%5,%6,%7}, {%8,%9}, {%0,%1,%2,%3};"
        : "+f"(c[0]), "+f"(c[1]), "+f"(c[2]), "+f"(c[3])
        : "r"(a[0]), "r"(a[1]), "r"(a[2]), "r"(a[3]), "r"(b[0]), "r"(b[1]));
}
__device__ __forceinline__ uint32_t pack_hi2(float a, float b) {
    return (uint32_t)__bfloat16_as_ushort(__float2bfloat16(a)) |
           ((uint32_t)__bfloat16_as_ushort(__float2bfloat16(b)) << 16);
}
__device__ __forceinline__ uint32_t pack_lo2(float a, float b) {
    float ra = a - __bfloat162float(__float2bfloat16(a));
    float rb = b - __bfloat162float(__float2bfloat16(b));
    return (uint32_t)__bfloat16_as_ushort(__float2bfloat16(ra)) |
           ((uint32_t)__bfloat16_as_ushort(__float2bfloat16(rb)) << 16);
}

// ---------------- reset / router / bookkeeping: R2 verbatim ----------------
__global__ void zero_kernel(float* __restrict__ out, size_t n) {
    size_t i = (size_t)blockIdx.x * blockDim.x + threadIdx.x;
    size_t stride = (size_t)gridDim.x * blockDim.x;
    for (; i < n; i += stride) out[i] = 0.f;
    if (blockIdx.x == 0 && threadIdx.x < kE) {
        g_counts[threadIdx.x] = 0;
        g_cursor[threadIdx.x] = 0;
        g_sumprob[threadIdx.x] = 0.f;
    }
}

__global__ void router_kernel(const float* __restrict__ x,
                              const float* __restrict__ Wgate, int T) {
    int warp = (blockIdx.x * blockDim.x + threadIdx.x) >> 5;
    int lane = threadIdx.x & 31;
    if (warp >= T) return;
    const float* xt = x + (size_t)warp * kD;

    float acc = 0.f;
#pragma unroll 4
    for (int d = 0; d < kD; ++d) acc += xt[d] * Wgate[d * kE + lane];

    float m = acc;
#pragma unroll
    for (int o = 16; o; o >>= 1) m = fmaxf(m, __shfl_xor_sync(0xffffffffu, m, o));
    float p = __expf(acc - m);
    float s = p;
#pragma unroll
    for (int o = 16; o; o >>= 1) s += __shfl_xor_sync(0xffffffffu, s, o);
    atomicAdd(&g_sumprob[lane], p / s);

    float v = acc;
    float topv[kK]; int topi[kK];
#pragma unroll
    for (int k = 0; k < kK; ++k) {
        float bv = v; int bi = lane;
#pragma unroll
        for (int o = 16; o; o >>= 1) {
            float ov = __shfl_xor_sync(0xffffffffu, bv, o);
            int   oi = __shfl_xor_sync(0xffffffffu, bi, o);
            if (ov > bv || (ov == bv && oi < bi)) { bv = ov; bi = oi; }
        }
        topv[k] = bv; topi[k] = bi;
        if (lane == bi) v = -INFINITY;
    }

    float mx = topv[0];
    float w[kK]; float se = 0.f;
#pragma unroll
    for (int k = 0; k < kK; ++k) { w[k] = __expf(topv[k] - mx); se += w[k]; }
#pragma unroll
    for (int k = 0; k < kK; ++k) {
        if (lane == k) {
            g_topi[warp * kK + k] = topi[k];
            g_topw[warp * kK + k] = w[k] / se;
            atomicAdd(&g_counts[topi[k]], 1);
        }
    }
}

__global__ void offsets_kernel() {
    if (threadIdx.x == 0) {
        int s = 0;
        for (int e = 0; e < kE; ++e) { g_offsets[e] = s; s += g_counts[e]; }
        g_offsets[kE] = s;
    }
}

__global__ void scatter_kernel(int T) {
    int idx = blockIdx.x * blockDim.x + threadIdx.x;
    if (idx >= T * kK) return;
    int e = g_topi[idx];
    int pos = g_offsets[e] + atomicAdd(&g_cursor[e], 1);
    g_rowtok[pos]   = idx / kK;
    g_rowscale[pos] = g_topw[idx];
}

__global__ void aux_kernel(float* __restrict__ out, int T, int out_size) {
    if (threadIdx.x == 0 && (size_t)out_size > (size_t)T * kD) {
        float a = 0.f;
        for (int e = 0; e < kE; ++e) a += g_sumprob[e] * (float)g_counts[e];
        out[(size_t)T * kD] = a / ((float)T * (float)T);
    }
}

// =========================================================================
// GEMM1: block 64(M) x 128(N), BK=16, 256 threads, fused gate+up.
// In-kernel fp32->bf16 hi/lo split during smem store. Single buffer + reg prefetch.
// smem planes (pitch 48B per 16-k row): AH@0(3072) AL@3072 GH@6144(6144)
//   GL@12288 UH@18432 UL@24576 -> 30720 B.
// Fragments (proven mapping): g=lane>>2,q=lane&3; A row wm*32+mt*16+g col 2q;
//   B n=wn*32+j*8+g, k=2q. a1=+8rows(+384B), a2=+8k(+16B); b1=+8k(+16B).
// =========================================================================
__global__ __launch_bounds__(256) void gemm1_mma(const float* __restrict__ x,
                                                 const float* __restrict__ Wg,
                                                 const float* __restrict__ Wu) {
    __shared__ __align__(16) char sm[30720];
    __shared__ int   toks[64];
    __shared__ float scls[64];
    const int e = blockIdx.z;
    const int base  = g_offsets[e];
    const int count = g_offsets[e + 1] - base;
    const int m0 = blockIdx.y * 64;
    if (m0 >= count) return;
    const int n0 = blockIdx.x * 128;
    const int tid = threadIdx.x, lane = tid & 31, wid = tid >> 5;
    const int wm = wid & 1, wn = wid >> 1, g = lane >> 2, q = lane & 3;

    if (tid < 64) {
        int r = m0 + tid;
        toks[tid] = g_rowtok[base + ((r < count) ? r : (count - 1))];
        scls[tid] = (r < count) ? g_rowscale[base + r] : 0.f;
    }
    __syncthreads();

    const int arow = tid >> 2, ac4 = tid & 3;       // A: 64 rows x 4 float4
    const int bn = tid & 127, bkq0 = tid >> 7;      // B: n fixed per thread, k-quads

    float4 ra;
    float rg[2][4], ru[2][4];

    auto load = [&](int s) {
        const int k0 = s * 16;
        ra = *(const float4*)(x + (size_t)toks[arow] * kD + k0 + ac4 * 4);
        const float* gp = Wg + ((size_t)e * kD + k0) * kI + n0 + bn;
        const float* up = Wu + ((size_t)e * kD + k0) * kI + n0 + bn;
#pragma unroll
        for (int t = 0; t < 2; ++t) {
            int kq = bkq0 + t * 2;
#pragma unroll
            for (int i = 0; i < 4; ++i) {
                rg[t][i] = gp[(size_t)(kq * 4 + i) * kI];
                ru[t][i] = up[(size_t)(kq * 4 + i) * kI];
            }
        }
    };
    auto store = [&]() {
        {   // A: rows k-contiguous
            uint32_t o = (uint32_t)(arow * 48 + ac4 * 8);
            *(uint32_t*)(sm + o)          = pack_hi2(ra.x, ra.y);
            *(uint32_t*)(sm + o + 4)      = pack_hi2(ra.z, ra.w);
            *(uint32_t*)(sm + 3072 + o)     = pack_lo2(ra.x, ra.y);
            *(uint32_t*)(sm + 3072 + o + 4) = pack_lo2(ra.z, ra.w);
        }
#pragma unroll
        for (int t = 0; t < 2; ++t) {   // B: [n][k] rows
            int kq = bkq0 + t * 2;
            uint32_t o = (uint32_t)(bn * 48 + kq * 8);
            *(uint32_t*)(sm + 6144 + o)      = pack_hi2(rg[t][0], rg[t][1]);
            *(uint32_t*)(sm + 6144 + o + 4)  = pack_hi2(rg[t][2], rg[t][3]);
            *(uint32_t*)(sm + 12288 + o)     = pack_lo2(rg[t][0], rg[t][1]);
            *(uint32_t*)(sm + 12288 + o + 4) = pack_lo2(rg[t][2], rg[t][3]);
            *(uint32_t*)(sm + 18432 + o)     = pack_hi2(ru[t][0], ru[t][1]);
            *(uint32_t*)(sm + 18432 + o + 4) = pack_hi2(ru[t][2], ru[t][3]);
            *(uint32_t*)(sm + 24576 + o)     = pack_lo2(ru[t][0], ru[t][1]);
            *(uint32_t*)(sm + 24576 + o + 4) = pack_lo2(ru[t][2], ru[t][3]);
        }
    };

    float cg[2][4][4] = {}, cu[2][4][4] = {};
    load(0); store();
    __syncthreads();

    const int S = kD / 16;   // 128
    for (int s = 0; s < S; ++s) {
        if (s + 1 < S) load(s + 1);
        uint32_t ah[2][4], al[2][4];
#pragma unroll
        for (int mt = 0; mt < 2; ++mt) {
            const char* o = sm + (wm * 32 + mt * 16 + g) * 48 + q * 4;
            ah[mt][0] = *(const uint32_t*)(o);
            ah[mt][1] = *(const uint32_t*)(o + 384);
            ah[mt][2] = *(const uint32_t*)(o + 16);
            ah[mt][3] = *(const uint32_t*)(o + 400);
            al[mt][0] = *(const uint32_t*)(o + 3072);
            al[mt][1] = *(const uint32_t*)(o + 3456);
            al[mt][2] = *(const uint32_t*)(o + 3088);
            al[mt][3] = *(const uint32_t*)(o + 3472);
        }
#pragma unroll
        for (int j = 0; j < 4; ++j) {
            const char* o = sm + 6144 + (wn * 32 + j * 8 + g) * 48 + q * 4;
            uint32_t gh[2] = { *(const uint32_t*)(o),          *(const uint32_t*)(o + 16) };
            uint32_t gl[2] = { *(const uint32_t*)(o + 6144),   *(const uint32_t*)(o + 6160) };
            uint32_t uh[2] = { *(const uint32_t*)(o + 12288),  *(const uint32_t*)(o + 12304) };
            uint32_t ul[2] = { *(const uint32_t*)(o + 18432),  *(const uint32_t*)(o + 18448) };
#pragma unroll
            for (int mt = 0; mt < 2; ++mt) {
                mma_bf16(cg[mt][j], ah[mt], gh);
                mma_bf16(cg[mt][j], ah[mt], gl);
                mma_bf16(cg[mt][j], al[mt], gh);
                mma_bf16(cu[mt][j], ah[mt], uh);
                mma_bf16(cu[mt][j], ah[mt], ul);
                mma_bf16(cu[mt][j], al[mt], uh);
            }
        }
        __syncthreads();
        if (s + 1 < S) store();
        __syncthreads();
    }

    // epilogue: H = silu(gate) * up * routing weight (fp32, R2 layout)
#pragma unroll
    for (int mt = 0; mt < 2; ++mt)
#pragma unroll
        for (int h = 0; h < 2; ++h) {
            int rl = wm * 32 + mt * 16 + g + h * 8;
            if (m0 + rl < count) {
                float sc = scls[rl];
                float* dst = g_H + (size_t)(base + m0 + rl) * kI + n0 + wn * 32 + q * 2;
#pragma unroll
                for (int j = 0; j < 4; ++j) {
                    float g0 = cg[mt][j][2 * h], g1 = cg[mt][j][2 * h + 1];
                    float u0 = cu[mt][j][2 * h], u1 = cu[mt][j][2 * h + 1];
                    float h0 = g0 / (1.f + __expf(-g0)) * u0 * sc;
                    float h1 = g1 / (1.f + __expf(-g1)) * u1 * sc;
                    *(float2*)(dst + j * 8) = make_float2(h0, h1);
                }
            }
        }
}

// =========================================================================
// GEMM2: block 64(M) x 128(N), BK=16. A=g_H fp32, B=Wd (K-major), atomicAdd out.
// smem planes: AH@0(3072) AL@3072 BH@6144(6144) BL@12288 -> 18432 B.
// =========================================================================
__global__ __launch_bounds__(256) void gemm2_mma(float* __restrict__ out,
                                                 const float* __restrict__ Wd) {
    __shared__ __align__(16) char sm[18432];
    __shared__ int toks[64];
    const int e = blockIdx.z;
    const int base  = g_offsets[e];
    const int count = g_offsets[e + 1] - base;
    const int m0 = blockIdx.y * 64;
    if (m0 >= count) return;
    const int n0 = blockIdx.x * 128;
    const int tid = threadIdx.x, lane = tid & 31, wid = tid >> 5;
    const int wm = wid & 1, wn = wid >> 1, g = lane >> 2, q = lane & 3;

    if (tid < 64) {
        int r = m0 + tid;
        toks[tid] = g_rowtok[base + ((r < count) ? r : (count - 1))];
    }
    __syncthreads();

    const int arow = tid >> 2, ac4 = tid & 3;
    const int bn = tid & 127, bkq0 = tid >> 7;
    const int arl = (m0 + arow < count) ? (m0 + arow) : (count - 1);
    const float* aptr = g_H + (size_t)(base + arl) * kI + ac4 * 4;

    float4 ra;
    float rb[2][4];

    auto load = [&](int s) {
        const int k0 = s * 16;
        ra = *(const float4*)(aptr + k0);
        const float* bp = Wd + ((size_t)e * kI + k0) * kD + n0 + bn;
#pragma unroll
        for (int t = 0; t < 2; ++t) {
            int kq = bkq0 + t * 2;
#pragma unroll
            for (int i = 0; i < 4; ++i)
                rb[t][i] = bp[(size_t)(kq * 4 + i) * kD];
        }
    };
    auto store = [&]() {
        {
            uint32_t o = (uint32_t)(arow * 48 + ac4 * 8);
            *(uint32_t*)(sm + o)          = pack_hi2(ra.x, ra.y);
            *(uint32_t*)(sm + o + 4)      = pack_hi2(ra.z, ra.w);
            *(uint32_t*)(sm + 3072 + o)     = pack_lo2(ra.x, ra.y);
            *(uint32_t*)(sm + 3072 + o + 4) = pack_lo2(ra.z, ra.w);
        }
#pragma unroll
        for (int t = 0; t < 2; ++t) {
            int kq = bkq0 + t * 2;
            uint32_t o = (uint32_t)(bn * 48 + kq * 8);
            *(uint32_t*)(sm + 6144 + o)      = pack_hi2(rb[t][0], rb[t][1]);
            *(uint32_t*)(sm + 6144 + o + 4)  = pack_hi2(rb[t][2], rb[t][3]);
            *(uint32_t*)(sm + 12288 + o)     = pack_lo2(rb[t][0], rb[t][1]);
            *(uint32_t*)(sm + 12288 + o + 4) = pack_lo2(rb[t][2], rb[t][3]);
        }
    };

    float c[2][4][4] = {};
    load(0); store();
    __syncthreads();

    const int S = kI / 16;   // 64
    for (int s = 0; s < S; ++s) {
        if (s + 1 < S) load(s + 1);
        uint32_t ah[2][4], al[2][4];
#pragma unroll
        for (int mt = 0; mt < 2; ++mt) {
            const char* o = sm + (wm * 32 + mt * 16 + g) * 48 + q * 4;
            ah[mt][0] = *(const uint32_t*)(o);
            ah[mt][1] = *(const uint32_t*)(o + 384);
            ah[mt][2] = *(const uint32_t*)(o + 16);
            ah[mt][3] = *(const uint32_t*)(o + 400);
            al[mt][0] = *(const uint32_t*)(o + 3072);
            al[mt][1] = *(const uint32_t*)(o + 3456);
            al[mt][2] = *(const uint32_t*)(o + 3088);
            al[mt][3] = *(const uint32_t*)(o + 3472);
        }
#pragma unroll
        for (int j = 0; j < 4; ++j) {
            const char* o = sm + 6144 + (wn * 32 + j * 8 + g) * 48 + q * 4;
            uint32_t bh[2] = { *(const uint32_t*)(o),        *(const uint32_t*)(o + 16) };
            uint32_t bl[2] = { *(const uint32_t*)(o + 6144), *(const uint32_t*)(o + 6160) };
#pragma unroll
            for (int mt = 0; mt < 2; ++mt) {
                mma_bf16(c[mt][j], ah[mt], bh);
                mma_bf16(c[mt][j], ah[mt], bl);
                mma_bf16(c[mt][j], al[mt], bh);
            }
        }
        __syncthreads();
        if (s + 1 < S) store();
        __syncthreads();
    }

    // epilogue: atomicAdd into out (R2-proven pattern)
#pragma unroll
    for (int mt = 0; mt < 2; ++mt)
#pragma unroll
        for (int h = 0; h < 2; ++h) {
            int rl = wm * 32 + mt * 16 + g + h * 8;
            if (m0 + rl < count) {
                int tok = toks[rl];
                float* op = out + (size_t)tok * kD + n0 + wn * 32 + q * 2;
#pragma unroll
                for (int j = 0; j < 4; ++j) {
                    atomicAdd(&op[j * 8],     c[mt][j][2 * h]);
                    atomicAdd(&op[j * 8 + 1], c[mt][j][2 * h + 1]);
                }
            }
        }
}

// ---------------- launch ----------------
extern "C" void kernel_launch(void* const* d_in, const int* in_sizes, int n_in,
                              void* d_out, int out_size) {
    const float* x     = (const float*)d_in[0];
    const float* Wgate = (const float*)d_in[1];
    const float* Wg    = (const float*)d_in[2];
    const float* Wu    = (const float*)d_in[3];
    const float* Wd    = (const float*)d_in[4];
    float* out = (float*)d_out;

    const int T = in_sizes[0] / kD;

    zero_kernel<<<2048, 256>>>(out, (size_t)out_size);
    router_kernel<<<(T + 7) / 8, 256>>>(x, Wgate, T);
    offsets_kernel<<<1, 32>>>();
    scatter_kernel<<<(T * kK + 255) / 256, 256>>>(T);
    aux_kernel<<<1, 32>>>(out, T, out_size);

    gemm1_mma<<<dim3(kI / 128, kMaxT / 64, kE), 256>>>(x, Wg, Wu);
    gemm2_mma<<<dim3(kD / 128, kMaxT / 64, kE), 256>>>(out, Wd);
}

// round 8
// speedup vs baseline: 2.1578x; 1.0738x over previous
#include <cuda_runtime.h>
#include <cuda_bf16.h>
#include <math.h>
#include <stdint.h>

constexpr int kD = 2048, kE = 32, kK = 8, kI = 1024, kMaxT = 8192;
constexpr int kMaxRows = kMaxT * kK;   // 65536

// ---------------- scratch (R6-proven set) ----------------
__device__ int   g_topi[kMaxRows];
__device__ float g_topw[kMaxRows];
__device__ int   g_rowtok[kMaxRows];
__device__ float g_rowscale[kMaxRows];
__device__ int   g_counts[kE];
__device__ int   g_offsets[kE + 1];
__device__ int   g_cursor[kE];
__device__ float g_sumprob[kE];
__device__ __align__(16) float g_H[(size_t)kMaxRows * kI];   // 256 MB scratch

// ---------------- helpers ----------------
__device__ __forceinline__ void mma_bf16(float* c, const uint32_t* a, const uint32_t* b) {
    asm volatile(
        "mma.sync.aligned.m16n8k16.row.col.f32.bf16.bf16.f32 "
        "{%0,%1,%2,%3}, {%4,%5,%6,%7}, {%8,%9}, {%0,%1,%2,%3};"
        : "+f"(c[0]), "+f"(c[1]), "+f"(c[2]), "+f"(c[3])
        : "r"(a[0]), "r"(a[1]), "r"(a[2]), "r"(a[3]), "r"(b[0]), "r"(b[1]));
}
__device__ __forceinline__ uint32_t pack_hi2(float a, float b) {
    return (uint32_t)__bfloat16_as_ushort(__float2bfloat16(a)) |
           ((uint32_t)__bfloat16_as_ushort(__float2bfloat16(b)) << 16);
}
__device__ __forceinline__ uint32_t pack_lo2(float a, float b) {
    float ra = a - __bfloat162float(__float2bfloat16(a));
    float rb = b - __bfloat162float(__float2bfloat16(b));
    return (uint32_t)__bfloat16_as_ushort(__float2bfloat16(ra)) |
           ((uint32_t)__bfloat16_as_ushort(__float2bfloat16(rb)) << 16);
}

// ---------------- reset / router / bookkeeping (R2/R6 verbatim) ----------------
__global__ void zero_kernel(float* __restrict__ out, size_t n) {
    size_t i = (size_t)blockIdx.x * blockDim.x + threadIdx.x;
    size_t stride = (size_t)gridDim.x * blockDim.x;
    for (; i < n; i += stride) out[i] = 0.f;
    if (blockIdx.x == 0 && threadIdx.x < kE) {
        g_counts[threadIdx.x] = 0;
        g_cursor[threadIdx.x] = 0;
        g_sumprob[threadIdx.x] = 0.f;
    }
}

__global__ void router_kernel(const float* __restrict__ x,
                              const float* __restrict__ Wgate, int T) {
    int warp = (blockIdx.x * blockDim.x + threadIdx.x) >> 5;
    int lane = threadIdx.x & 31;
    if (warp >= T) return;
    const float* xt = x + (size_t)warp * kD;

    float acc = 0.f;
#pragma unroll 4
    for (int d = 0; d < kD; ++d) acc += xt[d] * Wgate[d * kE + lane];

    float m = acc;
#pragma unroll
    for (int o = 16; o; o >>= 1) m = fmaxf(m, __shfl_xor_sync(0xffffffffu, m, o));
    float p = __expf(acc - m);
    float s = p;
#pragma unroll
    for (int o = 16; o; o >>= 1) s += __shfl_xor_sync(0xffffffffu, s, o);
    atomicAdd(&g_sumprob[lane], p / s);

    float v = acc;
    float topv[kK]; int topi[kK];
#pragma unroll
    for (int k = 0; k < kK; ++k) {
        float bv = v; int bi = lane;
#pragma unroll
        for (int o = 16; o; o >>= 1) {
            float ov = __shfl_xor_sync(0xffffffffu, bv, o);
            int   oi = __shfl_xor_sync(0xffffffffu, bi, o);
            if (ov > bv || (ov == bv && oi < bi)) { bv = ov; bi = oi; }
        }
        topv[k] = bv; topi[k] = bi;
        if (lane == bi) v = -INFINITY;
    }

    float mx = topv[0];
    float w[kK]; float se = 0.f;
#pragma unroll
    for (int k = 0; k < kK; ++k) { w[k] = __expf(topv[k] - mx); se += w[k]; }
#pragma unroll
    for (int k = 0; k < kK; ++k) {
        if (lane == k) {
            g_topi[warp * kK + k] = topi[k];
            g_topw[warp * kK + k] = w[k] / se;
            atomicAdd(&g_counts[topi[k]], 1);
        }
    }
}

__global__ void offsets_kernel() {
    if (threadIdx.x == 0) {
        int s = 0;
        for (int e = 0; e < kE; ++e) { g_offsets[e] = s; s += g_counts[e]; }
        g_offsets[kE] = s;
    }
}

__global__ void scatter_kernel(int T) {
    int idx = blockIdx.x * blockDim.x + threadIdx.x;
    if (idx >= T * kK) return;
    int e = g_topi[idx];
    int pos = g_offsets[e] + atomicAdd(&g_cursor[e], 1);
    g_rowtok[pos]   = idx / kK;
    g_rowscale[pos] = g_topw[idx];
}

__global__ void aux_kernel(float* __restrict__ out, int T, int out_size) {
    if (threadIdx.x == 0 && (size_t)out_size > (size_t)T * kD) {
        float a = 0.f;
        for (int e = 0; e < kE; ++e) a += g_sumprob[e] * (float)g_counts[e];
        out[(size_t)T * kD] = a / ((float)T * (float)T);
    }
}

// =========================================================================
// GEMM1: block 128(M) x 128(N), BK=16, 512 threads, fused gate+up.
// smem planes (pitch 48B/row, 128 rows = 6144B): AH@0 AL@6144 GH@12288
//   GL@18432 UH@24576 UL@30720 -> 36864 B (static, single-buffer + reg prefetch).
// Warps: wm=wid&3 (32 rows), wn=wid>>2 (32 cols). Fragment map proven in R6.
// =========================================================================
__global__ __launch_bounds__(512, 1) void gemm1_mma(const float* __restrict__ x,
                                                    const float* __restrict__ Wg,
                                                    const float* __restrict__ Wu) {
    __shared__ __align__(16) char sm[36864];
    __shared__ int   toks[128];
    __shared__ float scls[128];
    const int e = blockIdx.z;
    const int base  = g_offsets[e];
    const int count = g_offsets[e + 1] - base;
    const int m0 = blockIdx.y * 128;
    if (m0 >= count) return;
    const int n0 = blockIdx.x * 128;
    const int tid = threadIdx.x, lane = tid & 31, wid = tid >> 5;
    const int wm = wid & 3, wn = wid >> 2, g = lane >> 2, q = lane & 3;

    if (tid < 128) {
        int r = m0 + tid;
        toks[tid] = g_rowtok[base + ((r < count) ? r : (count - 1))];
        scls[tid] = (r < count) ? g_rowscale[base + r] : 0.f;
    }
    __syncthreads();

    const int arow = tid >> 2, ac4 = tid & 3;       // A: 128 rows x 4 float4
    const int bn = tid & 127, bkq = tid >> 7;       // B: n fixed, k-quad 0..3

    float4 ra;
    float rg[4], ru[4];

    auto load = [&](int s) {
        const int k0 = s * 16;
        ra = *(const float4*)(x + (size_t)toks[arow] * kD + k0 + ac4 * 4);
        const float* gp = Wg + ((size_t)e * kD + k0 + bkq * 4) * kI + n0 + bn;
        const float* up = Wu + ((size_t)e * kD + k0 + bkq * 4) * kI + n0 + bn;
#pragma unroll
        for (int i = 0; i < 4; ++i) {
            rg[i] = gp[(size_t)i * kI];
            ru[i] = up[(size_t)i * kI];
        }
    };
    auto store = [&]() {
        {
            uint32_t o = (uint32_t)(arow * 48 + ac4 * 8);
            *(uint32_t*)(sm + o)            = pack_hi2(ra.x, ra.y);
            *(uint32_t*)(sm + o + 4)        = pack_hi2(ra.z, ra.w);
            *(uint32_t*)(sm + 6144 + o)     = pack_lo2(ra.x, ra.y);
            *(uint32_t*)(sm + 6144 + o + 4) = pack_lo2(ra.z, ra.w);
        }
        {
            uint32_t o = (uint32_t)(bn * 48 + bkq * 8);
            *(uint32_t*)(sm + 12288 + o)     = pack_hi2(rg[0], rg[1]);
            *(uint32_t*)(sm + 12288 + o + 4) = pack_hi2(rg[2], rg[3]);
            *(uint32_t*)(sm + 18432 + o)     = pack_lo2(rg[0], rg[1]);
            *(uint32_t*)(sm + 18432 + o + 4) = pack_lo2(rg[2], rg[3]);
            *(uint32_t*)(sm + 24576 + o)     = pack_hi2(ru[0], ru[1]);
            *(uint32_t*)(sm + 24576 + o + 4) = pack_hi2(ru[2], ru[3]);
            *(uint32_t*)(sm + 30720 + o)     = pack_lo2(ru[0], ru[1]);
            *(uint32_t*)(sm + 30720 + o + 4) = pack_lo2(ru[2], ru[3]);
        }
    };

    float cg[2][4][4] = {}, cu[2][4][4] = {};
    load(0); store();
    __syncthreads();

    const int S = kD / 16;   // 128
    for (int s = 0; s < S; ++s) {
        if (s + 1 < S) load(s + 1);
        uint32_t ah[2][4], al[2][4];
#pragma unroll
        for (int mt = 0; mt < 2; ++mt) {
            const char* o = sm + (wm * 32 + mt * 16 + g) * 48 + q * 4;
            ah[mt][0] = *(const uint32_t*)(o);
            ah[mt][1] = *(const uint32_t*)(o + 384);
            ah[mt][2] = *(const uint32_t*)(o + 16);
            ah[mt][3] = *(const uint32_t*)(o + 400);
            al[mt][0] = *(const uint32_t*)(o + 6144);
            al[mt][1] = *(const uint32_t*)(o + 6528);
            al[mt][2] = *(const uint32_t*)(o + 6160);
            al[mt][3] = *(const uint32_t*)(o + 6544);
        }
#pragma unroll
        for (int j = 0; j < 4; ++j) {
            const char* o = sm + 12288 + (wn * 32 + j * 8 + g) * 48 + q * 4;
            uint32_t gh[2] = { *(const uint32_t*)(o),          *(const uint32_t*)(o + 16) };
            uint32_t gl[2] = { *(const uint32_t*)(o + 6144),   *(const uint32_t*)(o + 6160) };
            uint32_t uh[2] = { *(const uint32_t*)(o + 12288),  *(const uint32_t*)(o + 12304) };
            uint32_t ul[2] = { *(const uint32_t*)(o + 18432),  *(const uint32_t*)(o + 18448) };
#pragma unroll
            for (int mt = 0; mt < 2; ++mt) {
                mma_bf16(cg[mt][j], ah[mt], gh);
                mma_bf16(cg[mt][j], ah[mt], gl);
                mma_bf16(cg[mt][j], al[mt], gh);
                mma_bf16(cu[mt][j], ah[mt], uh);
                mma_bf16(cu[mt][j], ah[mt], ul);
                mma_bf16(cu[mt][j], al[mt], uh);
            }
        }
        __syncthreads();
        if (s + 1 < S) store();
        __syncthreads();
    }

    // epilogue: H = silu(gate) * up * routing weight
#pragma unroll
    for (int mt = 0; mt < 2; ++mt)
#pragma unroll
        for (int h = 0; h < 2; ++h) {
            int rl = wm * 32 + mt * 16 + g + h * 8;
            if (m0 + rl < count) {
                float sc = scls[rl];
                float* dst = g_H + (size_t)(base + m0 + rl) * kI + n0 + wn * 32 + q * 2;
#pragma unroll
                for (int j = 0; j < 4; ++j) {
                    float g0 = cg[mt][j][2 * h], g1 = cg[mt][j][2 * h + 1];
                    float u0 = cu[mt][j][2 * h], u1 = cu[mt][j][2 * h + 1];
                    float h0 = g0 / (1.f + __expf(-g0)) * u0 * sc;
                    float h1 = g1 / (1.f + __expf(-g1)) * u1 * sc;
                    *(float2*)(dst + j * 8) = make_float2(h0, h1);
                }
            }
        }
}

// =========================================================================
// GEMM2: block 128(M) x 128(N), BK=16, 256 threads. A=g_H fp32, B=Wd, atomicAdd.
// smem: AH@0(6144) AL@6144 BH@12288 BL@18432 -> 24576 B. 2 blocks/SM.
// Warps: wm=wid&3 (32 rows), wn=wid>>2 in 0..1 (64 cols, j=0..7).
// =========================================================================
__global__ __launch_bounds__(256) void gemm2_mma(float* __restrict__ out,
                                                 const float* __restrict__ Wd) {
    __shared__ __align__(16) char sm[24576];
    __shared__ int toks[128];
    const int e = blockIdx.z;
    const int base  = g_offsets[e];
    const int count = g_offsets[e + 1] - base;
    const int m0 = blockIdx.y * 128;
    if (m0 >= count) return;
    const int n0 = blockIdx.x * 128;
    const int tid = threadIdx.x, lane = tid & 31, wid = tid >> 5;
    const int wm = wid & 3, wn = wid >> 2, g = lane >> 2, q = lane & 3;

    if (tid < 128) {
        int r = m0 + tid;
        toks[tid] = g_rowtok[base + ((r < count) ? r : (count - 1))];
    }
    __syncthreads();

    const int arow = tid >> 1, ah8 = (tid & 1) * 8;   // A: 128 rows, 8-k halves
    const int bn = tid & 127, bk8 = (tid >> 7) * 8;   // B: n fixed, 8-k halves
    const int arl = (m0 + arow < count) ? (m0 + arow) : (count - 1);
    const float* aptr = g_H + (size_t)(base + arl) * kI + ah8;

    float4 ra0, ra1;
    float rb[8];

    auto load = [&](int s) {
        const int k0 = s * 16;
        ra0 = *(const float4*)(aptr + k0);
        ra1 = *(const float4*)(aptr + k0 + 4);
        const float* bp = Wd + ((size_t)e * kI + k0 + bk8) * kD + n0 + bn;
#pragma unroll
        for (int i = 0; i < 8; ++i) rb[i] = bp[(size_t)i * kD];
    };
    auto store = [&]() {
        {
            uint32_t o = (uint32_t)(arow * 48 + ah8 * 2);
            *(uint32_t*)(sm + o)             = pack_hi2(ra0.x, ra0.y);
            *(uint32_t*)(sm + o + 4)         = pack_hi2(ra0.z, ra0.w);
            *(uint32_t*)(sm + o + 8)         = pack_hi2(ra1.x, ra1.y);
            *(uint32_t*)(sm + o + 12)        = pack_hi2(ra1.z, ra1.w);
            *(uint32_t*)(sm + 6144 + o)      = pack_lo2(ra0.x, ra0.y);
            *(uint32_t*)(sm + 6144 + o + 4)  = pack_lo2(ra0.z, ra0.w);
            *(uint32_t*)(sm + 6144 + o + 8)  = pack_lo2(ra1.x, ra1.y);
            *(uint32_t*)(sm + 6144 + o + 12) = pack_lo2(ra1.z, ra1.w);
        }
        {
            uint32_t o = (uint32_t)(bn * 48 + bk8 * 2);
            *(uint32_t*)(sm + 12288 + o)      = pack_hi2(rb[0], rb[1]);
            *(uint32_t*)(sm + 12288 + o + 4)  = pack_hi2(rb[2], rb[3]);
            *(uint32_t*)(sm + 12288 + o + 8)  = pack_hi2(rb[4], rb[5]);
            *(uint32_t*)(sm + 12288 + o + 12) = pack_hi2(rb[6], rb[7]);
            *(uint32_t*)(sm + 18432 + o)      = pack_lo2(rb[0], rb[1]);
            *(uint32_t*)(sm + 18432 + o + 4)  = pack_lo2(rb[2], rb[3]);
            *(uint32_t*)(sm + 18432 + o + 8)  = pack_lo2(rb[4], rb[5]);
            *(uint32_t*)(sm + 18432 + o + 12) = pack_lo2(rb[6], rb[7]);
        }
    };

    float c[2][8][4] = {};
    load(0); store();
    __syncthreads();

    const int S = kI / 16;   // 64
    for (int s = 0; s < S; ++s) {
        if (s + 1 < S) load(s + 1);
        uint32_t ah[2][4], al[2][4];
#pragma unroll
        for (int mt = 0; mt < 2; ++mt) {
            const char* o = sm + (wm * 32 + mt * 16 + g) * 48 + q * 4;
            ah[mt][0] = *(const uint32_t*)(o);
            ah[mt][1] = *(const uint32_t*)(o + 384);
            ah[mt][2] = *(const uint32_t*)(o + 16);
            ah[mt][3] = *(const uint32_t*)(o + 400);
            al[mt][0] = *(const uint32_t*)(o + 6144);
            al[mt][1] = *(const uint32_t*)(o + 6528);
            al[mt][2] = *(const uint32_t*)(o + 6160);
            al[mt][3] = *(const uint32_t*)(o + 6544);
        }
#pragma unroll
        for (int j = 0; j < 8; ++j) {
            const char* o = sm + 12288 + (wn * 64 + j * 8 + g) * 48 + q * 4;
            uint32_t bh[2] = { *(const uint32_t*)(o),        *(const uint32_t*)(o + 16) };
            uint32_t bl[2] = { *(const uint32_t*)(o + 6144), *(const uint32_t*)(o + 6160) };
#pragma unroll
            for (int mt = 0; mt < 2; ++mt) {
                mma_bf16(c[mt][j], ah[mt], bh);
                mma_bf16(c[mt][j], ah[mt], bl);
                mma_bf16(c[mt][j], al[mt], bh);
            }
        }
        __syncthreads();
        if (s + 1 < S) store();
        __syncthreads();
    }

#pragma unroll
    for (int mt = 0; mt < 2; ++mt)
#pragma unroll
        for (int h = 0; h < 2; ++h) {
            int rl = wm * 32 + mt * 16 + g + h * 8;
            if (m0 + rl < count) {
                int tok = toks[rl];
                float* op = out + (size_t)tok * kD + n0 + wn * 64 + q * 2;
#pragma unroll
                for (int j = 0; j < 8; ++j) {
                    atomicAdd(&op[j * 8],     c[mt][j][2 * h]);
                    atomicAdd(&op[j * 8 + 1], c[mt][j][2 * h + 1]);
                }
            }
        }
}

// ---------------- launch ----------------
extern "C" void kernel_launch(void* const* d_in, const int* in_sizes, int n_in,
                              void* d_out, int out_size) {
    const float* x     = (const float*)d_in[0];
    const float* Wgate = (const float*)d_in[1];
    const float* Wg    = (const float*)d_in[2];
    const float* Wu    = (const float*)d_in[3];
    const float* Wd    = (const float*)d_in[4];
    float* out = (float*)d_out;

    const int T = in_sizes[0] / kD;

    zero_kernel<<<2048, 256>>>(out, (size_t)out_size);
    router_kernel<<<(T + 7) / 8, 256>>>(x, Wgate, T);
    offsets_kernel<<<1, 32>>>();
    scatter_kernel<<<(T * kK + 255) / 256, 256>>>(T);
    aux_kernel<<<1, 32>>>(out, T, out_size);

    gemm1_mma<<<dim3(kI / 128, kMaxT / 128, kE), 512>>>(x, Wg, Wu);
    gemm2_mma<<<dim3(kD / 128, kMaxT / 128, kE), 256>>>(out, Wd);
}